// round 1
// baseline (speedup 1.0000x reference)
#include <cuda_runtime.h>
#include <math.h>

// Problem constants (fixed shapes)
#define B  64
#define E  512
#define N  8192
#define M  64
#define AD 70          // M + 6
#define EPS 1e-8f

// ---------------- device scratch (no allocation allowed) ----------------
__device__ float g_k[B * M];
__device__ float g_knorm[B];
__device__ float g_beta[B];
__device__ float g_g[B];
__device__ float g_s[B * 3];
__device__ float g_y[B];
__device__ float g_S[B];      // softmax denominator
__device__ float g_Spow[B];   // sharpening denominator
__device__ float g_e[B * N];      // exp(beta*sim)
__device__ float g_wpow[B * N];   // w_s ^ y

__device__ __forceinline__ float softplus_f(float x) {
    return (x > 20.f) ? x : log1pf(expf(x));
}

// ---------------- K1: addressing vector + activations + zeroing ----------------
__global__ void k1_addr(const float* __restrict__ emb,
                        const float* __restrict__ W,
                        const float* __restrict__ bias,
                        float* __restrict__ out_md) {
    int b = blockIdx.x;
    int t = threadIdx.x;
    __shared__ float s_addr[AD];
    __shared__ float s_ksq;
    if (t == 0) s_ksq = 0.f;

    if (t < AD) {
        float acc = 0.f;
        const float* er = emb + (size_t)b * E;
        #pragma unroll 4
        for (int e = 0; e < E; e++)
            acc = fmaf(er[e], W[(size_t)e * AD + t], acc);
        s_addr[t] = acc + bias[t];
    }
    // zero the memory_data output region and the global accumulators
    if (t < M) out_md[b * M + t] = 0.f;
    if (t == M)     g_S[b]    = 0.f;
    if (t == M + 1) g_Spow[b] = 0.f;
    __syncthreads();

    if (t < M) {
        float kv = s_addr[t];
        g_k[b * M + t] = kv;
        atomicAdd(&s_ksq, kv * kv);
    }
    __syncthreads();

    if (t == 0) {
        g_knorm[b] = sqrtf(s_ksq);
        g_beta[b]  = softplus_f(s_addr[M]);
        g_g[b]     = 1.f / (1.f + expf(-s_addr[M + 1]));
        float a = s_addr[M + 2], c = s_addr[M + 3], d = s_addr[M + 4];
        float mx = fmaxf(a, fmaxf(c, d));
        float ea = expf(a - mx), eb = expf(c - mx), ec = expf(d - mx);
        float inv = 1.f / (ea + eb + ec);
        g_s[b * 3 + 0] = ea * inv;
        g_s[b * 3 + 1] = eb * inv;
        g_s[b * 3 + 2] = ec * inv;
        g_y[b] = 1.f + softplus_f(s_addr[M + 5]);
    }
}

// ---------------- K2: content addressing (pass 1 over memory, 128 MB) ----------------
// grid = (16, B), block = 256 (8 warps). Each warp handles 64 rows; warp-per-row
// float2 loads (fully coalesced 256B per row per warp), 4-row unroll for MLP.
__global__ void k2_sim(const float* __restrict__ mem) {
    int b     = blockIdx.y;
    int chunk = blockIdx.x;
    int warp  = threadIdx.x >> 5;
    int lane  = threadIdx.x & 31;

    __shared__ float sk[M];
    __shared__ float swsum[8];
    if (threadIdx.x < M) sk[threadIdx.x] = g_k[b * M + threadIdx.x];
    __syncthreads();

    float beta = g_beta[b];
    float kn   = g_knorm[b];
    float k0 = sk[lane * 2], k1 = sk[lane * 2 + 1];

    const float2* memp = (const float2*)(mem + (size_t)b * N * M);
    int n0 = chunk * 512 + warp * 64;

    float wsum = 0.f;
    for (int i = 0; i < 64; i += 4) {
        float2 mv[4];
        #pragma unroll
        for (int j = 0; j < 4; j++)
            mv[j] = memp[(size_t)(n0 + i + j) * 32 + lane];
        #pragma unroll
        for (int j = 0; j < 4; j++) {
            float dot = mv[j].x * k0 + mv[j].y * k1;
            float nsq = mv[j].x * mv[j].x + mv[j].y * mv[j].y;
            #pragma unroll
            for (int off = 16; off; off >>= 1) {
                dot += __shfl_xor_sync(0xffffffffu, dot, off);
                nsq += __shfl_xor_sync(0xffffffffu, nsq, off);
            }
            if (lane == 0) {
                float sim = dot / (sqrtf(nsq) * kn + EPS);
                float ev  = expf(beta * sim);   // no max-sub needed: |beta*sim| small
                g_e[b * N + n0 + i + j] = ev;
                wsum += ev;
            }
        }
    }
    if (lane == 0) swsum[warp] = wsum;
    __syncthreads();
    if (threadIdx.x == 0) {
        float s = 0.f;
        #pragma unroll
        for (int i = 0; i < 8; i++) s += swsum[i];
        atomicAdd(&g_S[b], s);
    }
}

// ---------------- K3: interpolate + circular shift + sharpen-pow + reduce ----------------
// One thread per (b, n). 8192 % 256 == 0 so each 256-block sits in a single batch.
__global__ void k3_shift(const float* __restrict__ w_prev) {
    int idx = blockIdx.x * blockDim.x + threadIdx.x;   // over B*N
    int b = idx >> 13;
    int n = idx & (N - 1);

    float S   = g_S[b];
    float gg  = g_g[b];
    float inv = gg / S;       // g * (1/S)
    float om  = 1.f - gg;
    float s0 = g_s[b * 3 + 0], s1 = g_s[b * 3 + 1], s2 = g_s[b * 3 + 2];

    const float* eb  = g_e    + (size_t)b * N;
    const float* wpb = w_prev + (size_t)b * N;
    int nm = (n + N - 1) & (N - 1);
    int np = (n + 1) & (N - 1);

    float wg_m = fmaf(inv, eb[nm], om * wpb[nm]);
    float wg_0 = fmaf(inv, eb[n],  om * wpb[n]);
    float wg_p = fmaf(inv, eb[np], om * wpb[np]);
    float ws   = s0 * wg_m + s1 * wg_0 + s2 * wg_p;

    float wpw = powf(ws, g_y[b]);
    g_wpow[idx] = wpw;

    // block reduce + one atomic per block
    float v = wpw;
    #pragma unroll
    for (int off = 16; off; off >>= 1)
        v += __shfl_xor_sync(0xffffffffu, v, off);
    __shared__ float sred[8];
    int warp = threadIdx.x >> 5, lane = threadIdx.x & 31;
    if (lane == 0) sred[warp] = v;
    __syncthreads();
    if (threadIdx.x == 0) {
        float s = 0.f;
        #pragma unroll
        for (int i = 0; i < 8; i++) s += sred[i];
        atomicAdd(&g_Spow[b], s);
    }
}

// ---------------- K4: normalize + read (pass 2 over memory, 128 MB) ----------------
// Reverse chunk order so the tail of pass 1 (most-recently cached in L2) is read first.
__global__ void k4_read(const float* __restrict__ mem,
                        float* __restrict__ out_md,
                        float* __restrict__ out_w) {
    int b     = blockIdx.y;
    int chunk = (gridDim.x - 1) - blockIdx.x;   // reversed traversal
    int warp  = threadIdx.x >> 5;
    int lane  = threadIdx.x & 31;

    __shared__ float sacc[M];
    if (threadIdx.x < M) sacc[threadIdx.x] = 0.f;
    __syncthreads();

    float inv = 1.f / (g_Spow[b] + EPS);
    const float2* memp = (const float2*)(mem + (size_t)b * N * M);
    const float*  wpw  = g_wpow + (size_t)b * N;
    int n0 = chunk * 512 + warp * 64;

    float a0 = 0.f, a1 = 0.f;
    for (int i = 0; i < 64; i += 4) {
        float2 mv[4];
        float  wv[4];
        #pragma unroll
        for (int j = 0; j < 4; j++) {
            mv[j] = memp[(size_t)(n0 + i + j) * 32 + lane];
            wv[j] = wpw[n0 + i + j] * inv;
        }
        #pragma unroll
        for (int j = 0; j < 4; j++) {
            a0 = fmaf(mv[j].x, wv[j], a0);
            a1 = fmaf(mv[j].y, wv[j], a1);
            if (lane == 0) out_w[(size_t)b * N + n0 + i + j] = wv[j];
        }
    }
    atomicAdd(&sacc[lane * 2],     a0);
    atomicAdd(&sacc[lane * 2 + 1], a1);
    __syncthreads();
    if (threadIdx.x < M)
        atomicAdd(&out_md[b * M + threadIdx.x], sacc[threadIdx.x]);
}

// ---------------- launch ----------------
extern "C" void kernel_launch(void* const* d_in, const int* in_sizes, int n_in,
                              void* d_out, int out_size) {
    const float* emb  = (const float*)d_in[0];   // [B,E]
    const float* wp   = (const float*)d_in[1];   // [B,N]
    const float* mem  = (const float*)d_in[2];   // [B,N,M]
    const float* W    = (const float*)d_in[3];   // [E,M+6]
    const float* bias = (const float*)d_in[4];   // [M+6]

    float* out    = (float*)d_out;
    float* out_md = out;                 // [B,M]  first output
    float* out_w  = out + (size_t)B * M; // [B,N]  second output

    k1_addr <<<B, 128>>>(emb, W, bias, out_md);
    k2_sim  <<<dim3(16, B), 256>>>(mem);
    k3_shift<<<(B * N) / 256, 256>>>(wp);
    k4_read <<<dim3(16, B), 256>>>(mem, out_md, out_w);
}

// round 3
// speedup vs baseline: 2.0271x; 2.0271x over previous
#include <cuda_runtime.h>
#include <math.h>

// Problem constants (fixed shapes)
#define B  64
#define E  512
#define N  8192
#define M  64
#define AD 70          // M + 6
#define EPS 1e-8f

// ---------------- device scratch (no allocation allowed) ----------------
__device__ float g_k[B * M];
__device__ float g_knorm[B];
__device__ float g_beta[B];
__device__ float g_g[B];
__device__ float g_s[B * 3];
__device__ float g_y[B];
__device__ float g_S[B];        // softmax denominator
__device__ float g_Spow[B];     // sharpening denominator
__device__ float g_e[B * N];    // exp(beta*sim)
__device__ float g_wpow[B * N]; // w_s ^ y

__device__ __forceinline__ float softplus_f(float x) {
    return (x > 20.f) ? x : log1pf(expf(x));
}

// ---------------- K1: addressing vector + activations + zeroing ----------------
// 512 threads: 4 chunks of E x 128-thread output slots (70 active).
__global__ void k1_addr(const float* __restrict__ emb,
                        const float* __restrict__ W,
                        const float* __restrict__ bias,
                        float* __restrict__ out_md) {
    int b   = blockIdx.x;
    int tid = threadIdx.x;
    int c   = tid >> 7;        // 0..3 chunk of E
    int t   = tid & 127;       // output slot

    __shared__ float part[4][AD];
    __shared__ float s_addr[AD];

    if (t < AD) {
        float acc = 0.f;
        const float* er = emb + (size_t)b * E + c * 128;
        const float* Wp = W + (size_t)(c * 128) * AD + t;
        #pragma unroll 8
        for (int e = 0; e < 128; e++)
            acc = fmaf(er[e], Wp[(size_t)e * AD], acc);
        part[c][t] = acc;
    }
    if (tid < M)      out_md[b * M + tid] = 0.f;
    if (tid == M)     g_S[b]    = 0.f;
    if (tid == M + 1) g_Spow[b] = 0.f;
    __syncthreads();

    if (tid < AD) {
        float v = part[0][tid] + part[1][tid] + part[2][tid] + part[3][tid] + bias[tid];
        s_addr[tid] = v;
        if (tid < M) g_k[b * M + tid] = v;
    }
    __syncthreads();

    if (tid < 32) {
        float a0 = s_addr[tid], a1 = s_addr[tid + 32];
        float sq = a0 * a0 + a1 * a1;
        #pragma unroll
        for (int off = 16; off; off >>= 1)
            sq += __shfl_xor_sync(0xffffffffu, sq, off);
        if (tid == 0) {
            g_knorm[b] = sqrtf(sq);
            g_beta[b]  = softplus_f(s_addr[M]);
            g_g[b]     = 1.f / (1.f + __expf(-s_addr[M + 1]));
            float a = s_addr[M + 2], cc = s_addr[M + 3], d = s_addr[M + 4];
            float mx = fmaxf(a, fmaxf(cc, d));
            float ea = __expf(a - mx), eb = __expf(cc - mx), ec = __expf(d - mx);
            float inv = 1.f / (ea + eb + ec);
            g_s[b * 3 + 0] = ea * inv;
            g_s[b * 3 + 1] = eb * inv;
            g_s[b * 3 + 2] = ec * inv;
            g_y[b] = 1.f + softplus_f(s_addr[M + 5]);
        }
    }
}

// ---------------- K2: content addressing (pass 1 over memory, 128 MB) ----------------
// grid = (16, B), block = 256 (8 warps). Quarter-warp (8 threads) per row:
// each thread holds 8 of the 64 row elements via two float4 loads; reductions
// are 3-level group shuffles whose each instruction reduces 4 rows at once.
__global__ void k2_sim(const float* __restrict__ mem) {
    int b     = blockIdx.y;
    int chunk = blockIdx.x;
    int warp  = threadIdx.x >> 5;
    int lane  = threadIdx.x & 31;
    int grp   = lane >> 3;     // 0..3 : which row of the 4-row batch
    int lg    = lane & 7;      // 0..7 : position within row

    __shared__ float sk[M];
    __shared__ float swsum[8];
    if (threadIdx.x < M) sk[threadIdx.x] = g_k[b * M + threadIdx.x];
    __syncthreads();

    float beta = g_beta[b];
    float kn   = g_knorm[b];
    float4 ka = *(const float4*)&sk[lg * 8];
    float4 kb = *(const float4*)&sk[lg * 8 + 4];

    const float4* memp = (const float4*)(mem + (size_t)b * N * M);
    int n0 = chunk * 512 + warp * 64;

    float wsum = 0.f;
    for (int i = 0; i < 64; i += 8) {
        int r0 = n0 + i + grp;
        int r1 = r0 + 4;
        float4 va0 = memp[(size_t)r0 * 16 + lg * 2];
        float4 vb0 = memp[(size_t)r0 * 16 + lg * 2 + 1];
        float4 va1 = memp[(size_t)r1 * 16 + lg * 2];
        float4 vb1 = memp[(size_t)r1 * 16 + lg * 2 + 1];

        #pragma unroll
        for (int u = 0; u < 2; u++) {
            float4 va = u ? va1 : va0;
            float4 vb = u ? vb1 : vb0;
            int r = u ? r1 : r0;
            float dot = va.x * ka.x + va.y * ka.y + va.z * ka.z + va.w * ka.w
                      + vb.x * kb.x + vb.y * kb.y + vb.z * kb.z + vb.w * kb.w;
            float nsq = va.x * va.x + va.y * va.y + va.z * va.z + va.w * va.w
                      + vb.x * vb.x + vb.y * vb.y + vb.z * vb.z + vb.w * vb.w;
            #pragma unroll
            for (int off = 4; off; off >>= 1) {
                dot += __shfl_xor_sync(0xffffffffu, dot, off);
                nsq += __shfl_xor_sync(0xffffffffu, nsq, off);
            }
            float sim = dot / (sqrtf(nsq) * kn + EPS);
            float ev  = __expf(beta * sim);   // no max-sub needed: |beta*sim| small
            if (lg == 0) g_e[b * N + r] = ev;
            wsum += ev;                       // counted 8x per row
        }
    }
    wsum *= 0.125f;
    #pragma unroll
    for (int off = 16; off; off >>= 1)
        wsum += __shfl_xor_sync(0xffffffffu, wsum, off);
    if (lane == 0) swsum[warp] = wsum;
    __syncthreads();
    if (threadIdx.x == 0) {
        float s = 0.f;
        #pragma unroll
        for (int i = 0; i < 8; i++) s += swsum[i];
        atomicAdd(&g_S[b], s);
    }
}

// ---------------- K3: interpolate + circular shift + sharpen-pow + reduce ----------------
__global__ void k3_shift(const float* __restrict__ w_prev) {
    int idx = blockIdx.x * blockDim.x + threadIdx.x;   // over B*N
    int b = idx >> 13;
    int n = idx & (N - 1);

    float S   = g_S[b];
    float gg  = g_g[b];
    float inv = gg / S;
    float om  = 1.f - gg;
    float s0 = g_s[b * 3 + 0], s1 = g_s[b * 3 + 1], s2 = g_s[b * 3 + 2];

    const float* eb  = g_e    + (size_t)b * N;
    const float* wpb = w_prev + (size_t)b * N;
    int nm = (n + N - 1) & (N - 1);
    int np = (n + 1) & (N - 1);

    float wg_m = fmaf(inv, eb[nm], om * wpb[nm]);
    float wg_0 = fmaf(inv, eb[n],  om * wpb[n]);
    float wg_p = fmaf(inv, eb[np], om * wpb[np]);
    float ws   = s0 * wg_m + s1 * wg_0 + s2 * wg_p;

    float wpw = __powf(ws, g_y[b]);   // ws > 0 strictly
    g_wpow[idx] = wpw;

    float v = wpw;
    #pragma unroll
    for (int off = 16; off; off >>= 1)
        v += __shfl_xor_sync(0xffffffffu, v, off);
    __shared__ float sred[8];
    int warp = threadIdx.x >> 5, lane = threadIdx.x & 31;
    if (lane == 0) sred[warp] = v;
    __syncthreads();
    if (threadIdx.x == 0) {
        float s = 0.f;
        #pragma unroll
        for (int i = 0; i < 8; i++) s += sred[i];
        atomicAdd(&g_Spow[b], s);
    }
}

// ---------------- K4: normalize + read (pass 2 over memory, 128 MB) ----------------
// Same quarter-warp layout; per-thread acc[8] in registers, cross-group shuffle
// reduce at the end, one shared stage, one global atomic batch per block.
// Both batch AND chunk axes reversed so k4's first wave re-reads what k2's
// last wave just left in L2 (126 MB capacity vs 128 MB tensor).
__global__ void k4_read(const float* __restrict__ mem,
                        float* __restrict__ out_md,
                        float* __restrict__ out_w) {
    int b     = (B - 1) - blockIdx.y;  // reversed batch traversal
    int chunk = 15 - blockIdx.x;       // reversed chunk traversal
    int warp  = threadIdx.x >> 5;
    int lane  = threadIdx.x & 31;
    int grp   = lane >> 3;
    int lg    = lane & 7;

    float inv = 1.f / (g_Spow[b] + EPS);
    const float4* memp = (const float4*)(mem + (size_t)b * N * M);
    const float*  wpw  = g_wpow + (size_t)b * N;
    int n0 = chunk * 512 + warp * 64;

    float acc[8] = {0.f, 0.f, 0.f, 0.f, 0.f, 0.f, 0.f, 0.f};

    for (int i = 0; i < 64; i += 8) {
        int r0 = n0 + i + grp;
        int r1 = r0 + 4;
        float4 va0 = memp[(size_t)r0 * 16 + lg * 2];
        float4 vb0 = memp[(size_t)r0 * 16 + lg * 2 + 1];
        float4 va1 = memp[(size_t)r1 * 16 + lg * 2];
        float4 vb1 = memp[(size_t)r1 * 16 + lg * 2 + 1];
        float wv0 = wpw[r0] * inv;
        float wv1 = wpw[r1] * inv;

        if (lg == 0) {
            out_w[(size_t)b * N + r0] = wv0;
            out_w[(size_t)b * N + r1] = wv1;
        }
        acc[0] = fmaf(va0.x, wv0, acc[0]);
        acc[1] = fmaf(va0.y, wv0, acc[1]);
        acc[2] = fmaf(va0.z, wv0, acc[2]);
        acc[3] = fmaf(va0.w, wv0, acc[3]);
        acc[4] = fmaf(vb0.x, wv0, acc[4]);
        acc[5] = fmaf(vb0.y, wv0, acc[5]);
        acc[6] = fmaf(vb0.z, wv0, acc[6]);
        acc[7] = fmaf(vb0.w, wv0, acc[7]);
        acc[0] = fmaf(va1.x, wv1, acc[0]);
        acc[1] = fmaf(va1.y, wv1, acc[1]);
        acc[2] = fmaf(va1.z, wv1, acc[2]);
        acc[3] = fmaf(va1.w, wv1, acc[3]);
        acc[4] = fmaf(vb1.x, wv1, acc[4]);
        acc[5] = fmaf(vb1.y, wv1, acc[5]);
        acc[6] = fmaf(vb1.z, wv1, acc[6]);
        acc[7] = fmaf(vb1.w, wv1, acc[7]);
    }

    // reduce across the 4 groups (lanes lg, lg+8, lg+16, lg+24)
    #pragma unroll
    for (int j = 0; j < 8; j++) {
        acc[j] += __shfl_xor_sync(0xffffffffu, acc[j], 8);
        acc[j] += __shfl_xor_sync(0xffffffffu, acc[j], 16);
    }

    __shared__ float sacc[8][M];
    if (grp == 0) {
        #pragma unroll
        for (int j = 0; j < 8; j++)
            sacc[warp][lg * 8 + j] = acc[j];
    }
    __syncthreads();
    if (threadIdx.x < M) {
        float s = 0.f;
        #pragma unroll
        for (int w = 0; w < 8; w++) s += sacc[w][threadIdx.x];
        atomicAdd(&out_md[b * M + threadIdx.x], s);
    }
}

// ---------------- launch ----------------
extern "C" void kernel_launch(void* const* d_in, const int* in_sizes, int n_in,
                              void* d_out, int out_size) {
    const float* emb  = (const float*)d_in[0];   // [B,E]
    const float* wp   = (const float*)d_in[1];   // [B,N]
    const float* mem  = (const float*)d_in[2];   // [B,N,M]
    const float* W    = (const float*)d_in[3];   // [E,M+6]
    const float* bias = (const float*)d_in[4];   // [M+6]

    float* out    = (float*)d_out;
    float* out_md = out;                 // [B,M]  first output
    float* out_w  = out + (size_t)B * M; // [B,N]  second output

    k1_addr <<<B, 512>>>(emb, W, bias, out_md);
    k2_sim  <<<dim3(16, B), 256>>>(mem);
    k3_shift<<<(B * N) / 256, 256>>>(wp);
    k4_read <<<dim3(16, B), 256>>>(mem, out_md, out_w);
}

// round 6
// speedup vs baseline: 2.0930x; 1.0325x over previous
#include <cuda_runtime.h>
#include <math.h>

// Problem constants (fixed shapes)
#define B  64
#define E  512
#define N  8192
#define M  64
#define AD 70          // M + 6
#define EPS 1e-8f

// ---------------- device scratch (no allocation allowed) ----------------
__device__ float g_k[B * M];
__device__ float g_knorm[B];
__device__ float g_beta[B];
__device__ float g_g[B];
__device__ float g_s[B * 3];
__device__ float g_y[B];
__device__ float g_S[B];        // softmax denominator
__device__ float g_Spow[B];     // sharpening denominator
__device__ float g_e[B * N];    // exp(beta*sim)

__device__ __forceinline__ float softplus_f(float x) {
    return (x > 20.f) ? x : log1pf(expf(x));
}

// ---------------- K1: addressing vector + activations + zeroing ----------------
__global__ void k1_addr(const float* __restrict__ emb,
                        const float* __restrict__ W,
                        const float* __restrict__ bias,
                        float* __restrict__ out_md) {
    int b   = blockIdx.x;
    int tid = threadIdx.x;
    int c   = tid >> 7;        // 0..3 chunk of E
    int t   = tid & 127;       // output slot

    __shared__ float part[4][AD];
    __shared__ float s_addr[AD];

    if (t < AD) {
        float acc = 0.f;
        const float* er = emb + (size_t)b * E + c * 128;
        const float* Wp = W + (size_t)(c * 128) * AD + t;
        #pragma unroll 8
        for (int e = 0; e < 128; e++)
            acc = fmaf(er[e], Wp[(size_t)e * AD], acc);
        part[c][t] = acc;
    }
    if (tid < M)      out_md[b * M + tid] = 0.f;
    if (tid == M)     g_S[b]    = 0.f;
    if (tid == M + 1) g_Spow[b] = 0.f;
    __syncthreads();

    if (tid < AD) {
        float v = part[0][tid] + part[1][tid] + part[2][tid] + part[3][tid] + bias[tid];
        s_addr[tid] = v;
        if (tid < M) g_k[b * M + tid] = v;
    }
    __syncthreads();

    if (tid < 32) {
        float a0 = s_addr[tid], a1 = s_addr[tid + 32];
        float sq = a0 * a0 + a1 * a1;
        #pragma unroll
        for (int off = 16; off; off >>= 1)
            sq += __shfl_xor_sync(0xffffffffu, sq, off);
        if (tid == 0) {
            g_knorm[b] = sqrtf(sq);
            g_beta[b]  = softplus_f(s_addr[M]);
            g_g[b]     = 1.f / (1.f + __expf(-s_addr[M + 1]));
            float a = s_addr[M + 2], cc = s_addr[M + 3], d = s_addr[M + 4];
            float mx = fmaxf(a, fmaxf(cc, d));
            float ea = __expf(a - mx), eb = __expf(cc - mx), ec = __expf(d - mx);
            float inv = 1.f / (ea + eb + ec);
            g_s[b * 3 + 0] = ea * inv;
            g_s[b * 3 + 1] = eb * inv;
            g_s[b * 3 + 2] = ec * inv;
            g_y[b] = 1.f + softplus_f(s_addr[M + 5]);
        }
    }
}

// ---------------- K2: content addressing (pass 1 over memory, 128 MB) ----------------
__global__ void k2_sim(const float* __restrict__ mem) {
    int b     = blockIdx.y;
    int chunk = blockIdx.x;
    int warp  = threadIdx.x >> 5;
    int lane  = threadIdx.x & 31;
    int grp   = lane >> 3;     // 0..3 : which row of the 4-row batch
    int lg    = lane & 7;      // 0..7 : position within row

    __shared__ float sk[M];
    __shared__ float swsum[8];
    if (threadIdx.x < M) sk[threadIdx.x] = g_k[b * M + threadIdx.x];
    __syncthreads();

    float beta = g_beta[b];
    float kn   = g_knorm[b];
    float4 ka = *(const float4*)&sk[lg * 8];
    float4 kb = *(const float4*)&sk[lg * 8 + 4];

    const float4* memp = (const float4*)(mem + (size_t)b * N * M);
    int n0 = chunk * 512 + warp * 64;

    float wsum = 0.f;
    #pragma unroll 2
    for (int i = 0; i < 64; i += 8) {
        int r0 = n0 + i + grp;
        int r1 = r0 + 4;
        float4 va0 = memp[(size_t)r0 * 16 + lg * 2];
        float4 vb0 = memp[(size_t)r0 * 16 + lg * 2 + 1];
        float4 va1 = memp[(size_t)r1 * 16 + lg * 2];
        float4 vb1 = memp[(size_t)r1 * 16 + lg * 2 + 1];

        #pragma unroll
        for (int u = 0; u < 2; u++) {
            float4 va = u ? va1 : va0;
            float4 vb = u ? vb1 : vb0;
            int r = u ? r1 : r0;
            float dot = va.x * ka.x + va.y * ka.y + va.z * ka.z + va.w * ka.w
                      + vb.x * kb.x + vb.y * kb.y + vb.z * kb.z + vb.w * kb.w;
            float nsq = va.x * va.x + va.y * va.y + va.z * va.z + va.w * va.w
                      + vb.x * vb.x + vb.y * vb.y + vb.z * vb.z + vb.w * vb.w;
            #pragma unroll
            for (int off = 4; off; off >>= 1) {
                dot += __shfl_xor_sync(0xffffffffu, dot, off);
                nsq += __shfl_xor_sync(0xffffffffu, nsq, off);
            }
            float sim = dot / (sqrtf(nsq) * kn + EPS);
            float ev  = __expf(beta * sim);   // no max-sub needed: |beta*sim| small
            if (lg == 0) g_e[b * N + r] = ev;
            wsum += ev;                       // counted 8x per row
        }
    }
    wsum *= 0.125f;
    #pragma unroll
    for (int off = 16; off; off >>= 1)
        wsum += __shfl_xor_sync(0xffffffffu, wsum, off);
    if (lane == 0) swsum[warp] = wsum;
    __syncthreads();
    if (threadIdx.x == 0) {
        float s = 0.f;
        #pragma unroll
        for (int i = 0; i < 8; i++) s += swsum[i];
        atomicAdd(&g_S[b], s);
    }
}

// ---------------- K34: fused shift + sharpen + read (pass 2, 128 MB) ----------------
// Each warp iteration handles 8 rows. All lanes compute ws/wpow for row
// n0+i+(lane&7) (4x lane redundancy is free: MUFU/FMA cost is per warp
// instruction); shfl.idx broadcasts wpow to the accumulating lanes.
// Accumulates UNNORMALIZED md and writes UNNORMALIZED wpow to out_w;
// k5 applies 1/Spow afterwards. Reversed traversal for L2 reuse of k2's tail.
__global__ void k34_read(const float* __restrict__ mem,
                         const float* __restrict__ w_prev,
                         float* __restrict__ out_md,
                         float* __restrict__ out_w) {
    int b     = (B - 1) - blockIdx.y;  // reversed batch traversal
    int chunk = 15 - blockIdx.x;       // reversed chunk traversal
    int warp  = threadIdx.x >> 5;
    int lane  = threadIdx.x & 31;
    int grp   = lane >> 3;
    int lg    = lane & 7;
    int l7    = lane & 7;

    float S    = g_S[b];
    float gg   = g_g[b];
    float invS = gg / S;
    float om   = 1.f - gg;
    float s0 = g_s[b * 3 + 0], s1 = g_s[b * 3 + 1], s2 = g_s[b * 3 + 2];
    float y  = g_y[b];

    const float4* memp = (const float4*)(mem + (size_t)b * N * M);
    const float*  eb   = g_e    + (size_t)b * N;
    const float*  wpb  = w_prev + (size_t)b * N;
    int n0 = chunk * 512 + warp * 64;

    float acc[8] = {0.f, 0.f, 0.f, 0.f, 0.f, 0.f, 0.f, 0.f};
    float spow = 0.f;

    #pragma unroll 2
    for (int i = 0; i < 64; i += 8) {
        int r0 = n0 + i + grp;
        int r1 = r0 + 4;
        float4 va0 = memp[(size_t)r0 * 16 + lg * 2];
        float4 vb0 = memp[(size_t)r0 * 16 + lg * 2 + 1];
        float4 va1 = memp[(size_t)r1 * 16 + lg * 2];
        float4 vb1 = memp[(size_t)r1 * 16 + lg * 2 + 1];

        // shift + sharpen for row rr = n0+i+(lane&7); lanes 8..31 duplicate 0..7
        int rr = n0 + i + l7;
        int nm = (rr + N - 1) & (N - 1);
        int np = (rr + 1) & (N - 1);
        float wg_m = fmaf(invS, eb[nm], om * wpb[nm]);
        float wg_0 = fmaf(invS, eb[rr], om * wpb[rr]);
        float wg_p = fmaf(invS, eb[np], om * wpb[np]);
        float ws   = s0 * wg_m + s1 * wg_0 + s2 * wg_p;
        float wv   = __powf(ws, y);          // ws > 0 strictly

        if (lane < 8) {
            out_w[(size_t)b * N + rr] = wv;  // unnormalized; k5 scales
            spow += wv;
        }
        float wv0 = __shfl_sync(0xffffffffu, wv, grp);
        float wv1 = __shfl_sync(0xffffffffu, wv, 4 + grp);

        acc[0] = fmaf(va0.x, wv0, acc[0]);
        acc[1] = fmaf(va0.y, wv0, acc[1]);
        acc[2] = fmaf(va0.z, wv0, acc[2]);
        acc[3] = fmaf(va0.w, wv0, acc[3]);
        acc[4] = fmaf(vb0.x, wv0, acc[4]);
        acc[5] = fmaf(vb0.y, wv0, acc[5]);
        acc[6] = fmaf(vb0.z, wv0, acc[6]);
        acc[7] = fmaf(vb0.w, wv0, acc[7]);
        acc[0] = fmaf(va1.x, wv1, acc[0]);
        acc[1] = fmaf(va1.y, wv1, acc[1]);
        acc[2] = fmaf(va1.z, wv1, acc[2]);
        acc[3] = fmaf(va1.w, wv1, acc[3]);
        acc[4] = fmaf(vb1.x, wv1, acc[4]);
        acc[5] = fmaf(vb1.y, wv1, acc[5]);
        acc[6] = fmaf(vb1.z, wv1, acc[6]);
        acc[7] = fmaf(vb1.w, wv1, acc[7]);
    }

    // reduce acc across the 4 groups (lanes lg, lg+8, lg+16, lg+24)
    #pragma unroll
    for (int j = 0; j < 8; j++) {
        acc[j] += __shfl_xor_sync(0xffffffffu, acc[j], 8);
        acc[j] += __shfl_xor_sync(0xffffffffu, acc[j], 16);
    }

    // reduce spow across warp (only lanes 0..7 hold nonzero)
    #pragma unroll
    for (int off = 16; off; off >>= 1)
        spow += __shfl_xor_sync(0xffffffffu, spow, off);

    __shared__ float sacc[8][M];
    __shared__ float sspow[8];
    if (grp == 0) {
        #pragma unroll
        for (int j = 0; j < 8; j++)
            sacc[warp][lg * 8 + j] = acc[j];
    }
    if (lane == 0) sspow[warp] = spow;
    __syncthreads();
    if (threadIdx.x < M) {
        float s = 0.f;
        #pragma unroll
        for (int w = 0; w < 8; w++) s += sacc[w][threadIdx.x];
        atomicAdd(&out_md[b * M + threadIdx.x], s);
    }
    if (threadIdx.x == M) {
        float s = 0.f;
        #pragma unroll
        for (int w = 0; w < 8; w++) s += sspow[w];
        atomicAdd(&g_Spow[b], s);
    }
}

// ---------------- K5: final normalization (L2-resident, ~2 MB) ----------------
__global__ void k5_norm(float* __restrict__ out_md, float* __restrict__ out_w) {
    int idx = blockIdx.x * blockDim.x + threadIdx.x;   // over B*N
    int b = idx >> 13;
    float inv = 1.f / (g_Spow[b] + EPS);
    out_w[idx] *= inv;
    if (idx < B * M) {
        int bb = idx >> 6;
        out_md[idx] *= 1.f / (g_Spow[bb] + EPS);
    }
}

// ---------------- launch ----------------
extern "C" void kernel_launch(void* const* d_in, const int* in_sizes, int n_in,
                              void* d_out, int out_size) {
    const float* emb  = (const float*)d_in[0];   // [B,E]
    const float* wp   = (const float*)d_in[1];   // [B,N]
    const float* mem  = (const float*)d_in[2];   // [B,N,M]
    const float* W    = (const float*)d_in[3];   // [E,M+6]
    const float* bias = (const float*)d_in[4];   // [M+6]

    float* out    = (float*)d_out;
    float* out_md = out;                 // [B,M]  first output
    float* out_w  = out + (size_t)B * M; // [B,N]  second output

    k1_addr <<<B, 512>>>(emb, W, bias, out_md);
    k2_sim  <<<dim3(16, B), 256>>>(mem);
    k34_read<<<dim3(16, B), 256>>>(mem, wp, out_md, out_w);
    k5_norm <<<(B * N) / 512, 512>>>(out_md, out_w);
}